// round 15
// baseline (speedup 1.0000x reference)
#include <cuda_runtime.h>

// FilterLayer: y[b,c,h,w] = sum_{i,j in 5x5} x_pad[b,c,h+i,w+j] * f[b,i*5+j,h,w]
// B=4, C=3, H=W=512, window=5, zero padding of 2.
// R15: R2 (best, 25.1us) with ONE change: the 25-tap loop is rolled at the
// outer (i) level so ptxas front-batches only ~5 f-LDGs per iteration instead
// of all 25. B300 spread model: MLP_p1=25 -> ~2x per-SM CTA completion spread
// (cross-CTA L1tex queue contention) -> DRAM-idle tails; MLP_p1=5 -> ~1.3x.
// Latency still covered: 64 warps x 5 LDG x 128B = 40KB/SM in flight.

#define IMG_H 512
#define IMG_W 512
#define TW 32
#define TH 8
#define HALO 2
#define TILE_R (TH + 2 * HALO)   // 12
#define TILE_C (TW + 2 * HALO)   // 36

__global__ __launch_bounds__(256, 8)
void filter_layer_kernel(const float* __restrict__ x,
                         const float* __restrict__ f,
                         float* __restrict__ out)
{
    __shared__ float xs[3][TILE_R][TILE_C];

    const int b  = blockIdx.z;
    const int w0 = blockIdx.x * TW;
    const int h0 = blockIdx.y * TH;
    const int tx = threadIdx.x;
    const int ty = threadIdx.y;
    const int tid = ty * TW + tx;

    const int HW = IMG_H * IMG_W;

    // ---- Stage 3-channel x tile with halo (zero-padded at borders) ----
    const float* xb = x + (size_t)b * 3 * HW;
    #pragma unroll
    for (int idx = tid; idx < 3 * TILE_R * TILE_C; idx += 256) {
        int c   = idx / (TILE_R * TILE_C);
        int rem = idx - c * (TILE_R * TILE_C);
        int r   = rem / TILE_C;
        int col = rem - r * TILE_C;
        int gr  = h0 + r - HALO;
        int gc  = w0 + col - HALO;
        float v = 0.0f;
        if ((unsigned)gr < (unsigned)IMG_H && (unsigned)gc < (unsigned)IMG_W)
            v = xb[c * HW + gr * IMG_W + gc];
        xs[c][r][col] = v;
    }
    __syncthreads();

    // ---- Per-pixel 25-tap weighted sum, f value shared across 3 channels ----
    const int h = h0 + ty;
    const int w = w0 + tx;
    const float* fp = f + (size_t)b * 25 * HW + h * IMG_W + w;

    float a0 = 0.0f, a1 = 0.0f, a2 = 0.0f;

    // Outer loop deliberately NOT unrolled: caps the f-LDG front batch at 5
    // per iteration (MLP_p1 ~ 5) to kill cross-CTA L1tex-queue spread.
    #pragma unroll 1
    for (int i = 0; i < 5; ++i) {
        const float* fpi = fp + (size_t)(i * 5) * HW;
        #pragma unroll
        for (int j = 0; j < 5; ++j) {
            const float fv = fpi[(size_t)j * HW];
            a0 = fmaf(xs[0][ty + i][tx + j], fv, a0);
            a1 = fmaf(xs[1][ty + i][tx + j], fv, a1);
            a2 = fmaf(xs[2][ty + i][tx + j], fv, a2);
        }
    }

    float* op = out + (size_t)b * 3 * HW + h * IMG_W + w;
    op[0]              = a0;
    op[(size_t)HW]     = a1;
    op[(size_t)2 * HW] = a2;
}

extern "C" void kernel_launch(void* const* d_in, const int* in_sizes, int n_in,
                              void* d_out, int out_size)
{
    const float* x = (const float*)d_in[0];
    const float* f = (const float*)d_in[1];
    float* out = (float*)d_out;

    dim3 block(TW, TH, 1);                       // 256 threads
    dim3 grid(IMG_W / TW, IMG_H / TH, 4);        // 16 x 64 x 4 = 4096 blocks
    filter_layer_kernel<<<grid, block>>>(x, f, out);
}

// round 16
// speedup vs baseline: 1.2901x; 1.2901x over previous
#include <cuda_runtime.h>

// FilterLayer: y[b,c,h,w] = sum_{i,j in 5x5} x_pad[b,c,h+i,w+j] * f[b,i*5+j,h,w]
// B=4, C=3, H=W=512, window=5, zero padding of 2.
// R16: R2 with tile reshaped 32x8 -> 64x4 (same 256 threads, 1px/thread,
// same grid count, full 25-unroll). Purpose: DRAM burst length. f's page =
// one image row = 2KB; a 32-wide block drains only 128B per (k,row) page
// visit -> ~820K row activations for the 105MB f stream (activation-limited,
// ~55% efficiency). 64-wide tiles pull 256B contiguous per visit and halve
// page activations. Everything else byte-identical to R2.

#define IMG_H 512
#define IMG_W 512
#define TW 64
#define TH 4
#define NTHREADS (TW * TH)        // 256
#define HALO 2
#define TILE_R (TH + 2 * HALO)    // 8
#define TILE_C (TW + 2 * HALO)    // 68

__global__ __launch_bounds__(NTHREADS, 8)
void filter_layer_kernel(const float* __restrict__ x,
                         const float* __restrict__ f,
                         float* __restrict__ out)
{
    __shared__ float xs[3][TILE_R][TILE_C];

    const int b  = blockIdx.z;
    const int w0 = blockIdx.x * TW;
    const int h0 = blockIdx.y * TH;
    const int tx = threadIdx.x;          // 0..63
    const int ty = threadIdx.y;          // 0..3
    const int tid = ty * TW + tx;

    const int HW = IMG_H * IMG_W;

    // ---- Stage 3-channel x tile with halo (zero-padded at borders) ----
    const float* xb = x + (size_t)b * 3 * HW;
    for (int idx = tid; idx < 3 * TILE_R * TILE_C; idx += NTHREADS) {
        int c   = idx / (TILE_R * TILE_C);
        int rem = idx - c * (TILE_R * TILE_C);
        int r   = rem / TILE_C;
        int col = rem - r * TILE_C;
        int gr  = h0 + r - HALO;
        int gc  = w0 + col - HALO;
        float v = 0.0f;
        if ((unsigned)gr < (unsigned)IMG_H && (unsigned)gc < (unsigned)IMG_W)
            v = __ldg(xb + c * HW + gr * IMG_W + gc);
        xs[c][r][col] = v;
    }
    __syncthreads();

    // ---- Per-pixel 25-tap weighted sum, f value shared across 3 channels ----
    const int h = h0 + ty;
    const int w = w0 + tx;
    const float* fp = f + (size_t)b * 25 * HW + h * IMG_W + w;

    float a0 = 0.0f, a1 = 0.0f, a2 = 0.0f;
    #pragma unroll
    for (int k = 0; k < 25; ++k) {
        const int i = k / 5;
        const int j = k % 5;
        // streaming load: f is touched exactly once -> evict-first policy
        const float fv = __ldcs(fp + (size_t)k * HW);
        a0 = fmaf(xs[0][ty + i][tx + j], fv, a0);
        a1 = fmaf(xs[1][ty + i][tx + j], fv, a1);
        a2 = fmaf(xs[2][ty + i][tx + j], fv, a2);
    }

    float* op = out + (size_t)b * 3 * HW + h * IMG_W + w;
    op[0]              = a0;
    op[(size_t)HW]     = a1;
    op[(size_t)2 * HW] = a2;
}

extern "C" void kernel_launch(void* const* d_in, const int* in_sizes, int n_in,
                              void* d_out, int out_size)
{
    const float* x = (const float*)d_in[0];
    const float* f = (const float*)d_in[1];
    float* out = (float*)d_out;

    dim3 block(TW, TH, 1);                       // 256 threads
    dim3 grid(IMG_W / TW, IMG_H / TH, 4);        // 8 x 128 x 4 = 4096 blocks
    filter_layer_kernel<<<grid, block>>>(x, f, out);
}